// round 5
// baseline (speedup 1.0000x reference)
#include <cuda_runtime.h>

// ---------------------------------------------------------------------------
// CausalEdgeAttention — algebraically reduced.
//   out = edge_attr + 0.5*((relu(ctx@W1+b1) * g) @ M + const8)
//   ctx = 0.5*(nf[src]+nf[tgt]);  M = n_W2@Wv@Wo@Wp (256x8)
//   BN stats of h over all E edges (pass 1), folded into Mg/const8, pass 2
//   recomputes h and emits output. Edge-encoder branch is dead code.
// R2: f32x2 packed math, MLP-oriented kStats (2-edge unroll, 444x128),
//     2-edge-per-thread kOut, folding kernels merged into one.
// ---------------------------------------------------------------------------

#define STATS_BLOCKS 444          // 3 blocks/SM * 148 SMs, one wave
#define STATS_WARPS  (STATS_BLOCKS * 4)

__device__ __align__(16) float g_U[256 * 8];
__device__ __align__(16) float g_V[256 * 8];
__device__ __align__(16) float g_M[256 * 8];
__device__ __align__(16) float g_Mg[256 * 8];
__device__ float g_c1[256];
__device__ float g_c2[256];
__device__ float g_c3[8];
__device__ __align__(16) float g_const8[8];
__device__ float g_part[STATS_BLOCKS * 512];

// ---- packed f32x2 helpers -------------------------------------------------
__device__ __forceinline__ unsigned long long pk2(float lo, float hi) {
    unsigned long long r;
    asm("mov.b64 %0, {%1, %2};" : "=l"(r) : "f"(lo), "f"(hi));
    return r;
}
__device__ __forceinline__ void upk2(unsigned long long v, float& lo, float& hi) {
    asm("mov.b64 {%0, %1}, %2;" : "=f"(lo), "=f"(hi) : "l"(v));
}
#define FMA2(d, a, b, c) asm("fma.rn.f32x2 %0, %1, %2, %3;" : "=l"(d) : "l"(a), "l"(b), "l"(c))
#define MUL2(d, a, b)    asm("mul.rn.f32x2 %0, %1, %2;" : "=l"(d) : "l"(a), "l"(b))
#define ADD2(d, a, b)    asm("add.rn.f32x2 %0, %1, %2;" : "=l"(d) : "l"(a), "l"(b))

#define HALF2C 0x3F0000003F000000ULL   // (0.5f, 0.5f)

// ---- pass 1: batch stats of h = relu(ctx@W1+b1) ---------------------------
// warp-per-edge-stream, lane owns 8 columns, 2-edge unroll for MLP.
__global__ void __launch_bounds__(128) kStats(
    const float* __restrict__ nf, const int* __restrict__ ei,
    const float* __restrict__ W1, const float* __restrict__ b1, int E) {
    __shared__ float psum[4][256];
    __shared__ float psq[4][256];

    int tid = threadIdx.x;
    int lane = tid & 31;
    int w = tid >> 5;                    // 0..3

    // packed weights: w2[k][p] = (W1[2p][j], W1[2p+1][j]), j = 32k+lane
    unsigned long long w2[8][4];
    float bb[8];
#pragma unroll
    for (int k = 0; k < 8; k++) {
        int j = k * 32 + lane;
        bb[k] = b1[j];
#pragma unroll
        for (int p = 0; p < 4; p++)
            w2[k][p] = pk2(W1[(2 * p) * 256 + j], W1[(2 * p + 1) * 256 + j]);
    }

    float s[8], q[8];
#pragma unroll
    for (int k = 0; k < 8; k++) { s[k] = 0.f; q[k] = 0.f; }

    int gw = blockIdx.x * 4 + w;
    int per = (E + STATS_WARPS - 1) / STATS_WARPS;
    int e0 = gw * per;
    int e1 = min(e0 + per, E);

    const ulonglong4* nfq = (const ulonglong4*)nf;
    const unsigned long long H2 = HALF2C;

    for (int e = e0; e < e1; e += 2) {
        int ia0 = ei[e], ib0 = ei[E + e];
        bool two = (e + 1 < e1);
        int et = two ? (e + 1) : e;
        int ia1 = ei[et], ib1 = ei[E + et];

        ulonglong4 A0 = nfq[ia0], B0 = nfq[ib0];
        ulonglong4 A1 = nfq[ia1], B1 = nfq[ib1];

        unsigned long long c0[4], c1[4];
        ADD2(c0[0], A0.x, B0.x); ADD2(c0[1], A0.y, B0.y);
        ADD2(c0[2], A0.z, B0.z); ADD2(c0[3], A0.w, B0.w);
        ADD2(c1[0], A1.x, B1.x); ADD2(c1[1], A1.y, B1.y);
        ADD2(c1[2], A1.z, B1.z); ADD2(c1[3], A1.w, B1.w);
#pragma unroll
        for (int p = 0; p < 4; p++) { MUL2(c0[p], c0[p], H2); MUL2(c1[p], c1[p], H2); }

#pragma unroll
        for (int k = 0; k < 8; k++) {
            unsigned long long a0, a1;
            MUL2(a0, c0[0], w2[k][0]); FMA2(a0, c0[1], w2[k][1], a0);
            MUL2(a1, c0[2], w2[k][2]); FMA2(a1, c0[3], w2[k][3], a1);
            ADD2(a0, a0, a1);
            float lo, hi; upk2(a0, lo, hi);
            float h = fmaxf(lo + hi + bb[k], 0.f);
            s[k] += h;
            q[k] = fmaf(h, h, q[k]);
        }
        if (two) {
#pragma unroll
            for (int k = 0; k < 8; k++) {
                unsigned long long a0, a1;
                MUL2(a0, c1[0], w2[k][0]); FMA2(a0, c1[1], w2[k][1], a0);
                MUL2(a1, c1[2], w2[k][2]); FMA2(a1, c1[3], w2[k][3], a1);
                ADD2(a0, a0, a1);
                float lo, hi; upk2(a0, lo, hi);
                float h = fmaxf(lo + hi + bb[k], 0.f);
                s[k] += h;
                q[k] = fmaf(h, h, q[k]);
            }
        }
    }

#pragma unroll
    for (int k = 0; k < 8; k++) {
        psum[w][k * 32 + lane] = s[k];
        psq[w][k * 32 + lane] = q[k];
    }
    __syncthreads();

    for (int c = tid; c < 256; c += 128) {
        float ts = 0.f, tq = 0.f;
#pragma unroll
        for (int ww = 0; ww < 4; ww++) { ts += psum[ww][c]; tq += psq[ww][c]; }
        g_part[blockIdx.x * 512 + c] = ts;
        g_part[blockIdx.x * 512 + 256 + c] = tq;
    }
}

// ---- weight folding + BN finalize, single kernel (1 block, 1024 thr) ------
__global__ void __launch_bounds__(1024) kFoldFin(
    const float* __restrict__ Wo, const float* __restrict__ Wp,
    const float* __restrict__ nb2, const float* __restrict__ Wv,
    const float* __restrict__ bv, const float* __restrict__ bo,
    const float* __restrict__ nW2, const float* __restrict__ bp,
    const float* __restrict__ gamma, const float* __restrict__ beta,
    float invE) {
    int tid = threadIdx.x;

    // stage A: U = Wo@Wp ; c1 = nb2@Wv + bv
    for (int t = tid; t < 2304; t += 1024) {
        if (t < 2048) {
            int i = t >> 3, d = t & 7;
            float a0 = 0.f, a1 = 0.f, a2 = 0.f, a3 = 0.f;
            for (int k = 0; k < 256; k += 4) {
                a0 = fmaf(Wo[i * 256 + k],     Wp[k * 8 + d],       a0);
                a1 = fmaf(Wo[i * 256 + k + 1], Wp[(k + 1) * 8 + d], a1);
                a2 = fmaf(Wo[i * 256 + k + 2], Wp[(k + 2) * 8 + d], a2);
                a3 = fmaf(Wo[i * 256 + k + 3], Wp[(k + 3) * 8 + d], a3);
            }
            g_U[t] = (a0 + a1) + (a2 + a3);
        } else {
            int i = t - 2048;
            float a0 = bv[i], a1 = 0.f, a2 = 0.f, a3 = 0.f;
            for (int k = 0; k < 256; k += 4) {
                a0 = fmaf(nb2[k],     Wv[k * 256 + i],       a0);
                a1 = fmaf(nb2[k + 1], Wv[(k + 1) * 256 + i], a1);
                a2 = fmaf(nb2[k + 2], Wv[(k + 2) * 256 + i], a2);
                a3 = fmaf(nb2[k + 3], Wv[(k + 3) * 256 + i], a3);
            }
            g_c1[i] = (a0 + a1) + (a2 + a3);
        }
    }
    __syncthreads();

    // stage B: V = Wv@U ; c2 = c1@Wo + bo
    for (int t = tid; t < 2304; t += 1024) {
        if (t < 2048) {
            int i = t >> 3, d = t & 7;
            float a0 = 0.f, a1 = 0.f, a2 = 0.f, a3 = 0.f;
            for (int k = 0; k < 256; k += 4) {
                a0 = fmaf(Wv[i * 256 + k],     g_U[k * 8 + d],       a0);
                a1 = fmaf(Wv[i * 256 + k + 1], g_U[(k + 1) * 8 + d], a1);
                a2 = fmaf(Wv[i * 256 + k + 2], g_U[(k + 2) * 8 + d], a2);
                a3 = fmaf(Wv[i * 256 + k + 3], g_U[(k + 3) * 8 + d], a3);
            }
            g_V[t] = (a0 + a1) + (a2 + a3);
        } else {
            int i = t - 2048;
            float a0 = bo[i], a1 = 0.f, a2 = 0.f, a3 = 0.f;
            for (int k = 0; k < 256; k += 4) {
                a0 = fmaf(g_c1[k],     Wo[k * 256 + i],       a0);
                a1 = fmaf(g_c1[k + 1], Wo[(k + 1) * 256 + i], a1);
                a2 = fmaf(g_c1[k + 2], Wo[(k + 2) * 256 + i], a2);
                a3 = fmaf(g_c1[k + 3], Wo[(k + 3) * 256 + i], a3);
            }
            g_c2[i] = (a0 + a1) + (a2 + a3);
        }
    }
    __syncthreads();

    // stage C: M = nW2@V ; c3 = c2@Wp + bp
    for (int t = tid; t < 2056; t += 1024) {
        if (t < 2048) {
            int i = t >> 3, d = t & 7;
            float a0 = 0.f, a1 = 0.f, a2 = 0.f, a3 = 0.f;
            for (int k = 0; k < 256; k += 4) {
                a0 = fmaf(nW2[i * 256 + k],     g_V[k * 8 + d],       a0);
                a1 = fmaf(nW2[i * 256 + k + 1], g_V[(k + 1) * 8 + d], a1);
                a2 = fmaf(nW2[i * 256 + k + 2], g_V[(k + 2) * 8 + d], a2);
                a3 = fmaf(nW2[i * 256 + k + 3], g_V[(k + 3) * 8 + d], a3);
            }
            g_M[t] = (a0 + a1) + (a2 + a3);
        } else {
            int d = t - 2048;
            float acc = bp[d];
            for (int k = 0; k < 256; k++) acc = fmaf(g_c2[k], Wp[k * 8 + d], acc);
            g_c3[d] = acc;
        }
    }
    __syncthreads();

    // finalize BN: fold into Mg / const8  (first 256 threads)
    __shared__ float sh[256];
    if (tid < 256) {
        int j = tid;
        float s = 0.f, q = 0.f;
        for (int b = 0; b < STATS_BLOCKS; b++) {
            s += g_part[b * 512 + j];
            q += g_part[b * 512 + 256 + j];
        }
        float mu = s * invE;
        float var = q * invE - mu * mu;
        float gg = gamma[j] * rsqrtf(var + 1e-5f);
        sh[j] = beta[j] - mu * gg;
#pragma unroll
        for (int d = 0; d < 8; d++) g_Mg[j * 8 + d] = gg * g_M[j * 8 + d];
    }
    __syncthreads();
    if (tid < 256) {
        int w = tid >> 5, lane = tid & 31;   // warp w -> const8[w]
        float acc = 0.f;
        for (int jj = lane; jj < 256; jj += 32) acc += sh[jj] * g_M[jj * 8 + w];
#pragma unroll
        for (int off = 16; off; off >>= 1)
            acc += __shfl_xor_sync(0xffffffffu, acc, off);
        if (lane == 0) g_const8[w] = acc + g_c3[w];
    }
}

// ---- pass 2: output, 2 edges per thread -----------------------------------
__global__ void __launch_bounds__(256) kOut(
    const float* __restrict__ nf, const int* __restrict__ ei,
    const float* __restrict__ W1, const float* __restrict__ b1,
    const float* __restrict__ ea, float* __restrict__ out, int E) {
    __shared__ ulonglong2 sW[512];   // col j -> [2j],[2j+1] : 4 packed w pairs
    __shared__ ulonglong2 sM[512];   // col j -> 4 packed Mg pairs
    __shared__ float sB[256];
    __shared__ unsigned long long sC[4];

    int tid = threadIdx.x;
    for (int i = tid; i < 512; i += 256) {
        int j = i >> 1, h = i & 1;
        int p = 2 * h;
        ulonglong2 wv;
        wv.x = pk2(W1[(2 * p) * 256 + j],     W1[(2 * p + 1) * 256 + j]);
        wv.y = pk2(W1[(2 * p + 2) * 256 + j], W1[(2 * p + 3) * 256 + j]);
        sW[i] = wv;
        sM[i] = ((const ulonglong2*)g_Mg)[i];
    }
    sB[tid] = b1[tid];
    if (tid < 4) sC[tid] = ((const unsigned long long*)g_const8)[tid];
    __syncthreads();

    int base = blockIdx.x * 512;
    int eA = base + tid;
    int eB = base + 256 + tid;
    bool vA = eA < E, vB = eB < E;
    int eAc = vA ? eA : 0, eBc = vB ? eB : 0;

    int ia0 = ei[eAc], ib0 = ei[E + eAc];
    int ia1 = ei[eBc], ib1 = ei[E + eBc];
    const ulonglong4* nfq = (const ulonglong4*)nf;
    ulonglong4 A0 = nfq[ia0], B0 = nfq[ib0];
    ulonglong4 A1 = nfq[ia1], B1 = nfq[ib1];

    const unsigned long long H2 = HALF2C;
    unsigned long long cA[4], cB[4];
    ADD2(cA[0], A0.x, B0.x); ADD2(cA[1], A0.y, B0.y);
    ADD2(cA[2], A0.z, B0.z); ADD2(cA[3], A0.w, B0.w);
    ADD2(cB[0], A1.x, B1.x); ADD2(cB[1], A1.y, B1.y);
    ADD2(cB[2], A1.z, B1.z); ADD2(cB[3], A1.w, B1.w);
#pragma unroll
    for (int p = 0; p < 4; p++) { MUL2(cA[p], cA[p], H2); MUL2(cB[p], cB[p], H2); }

    unsigned long long yA[4], yB[4];
#pragma unroll
    for (int p = 0; p < 4; p++) { yA[p] = 0ull; yB[p] = 0ull; }

#pragma unroll 4
    for (int j = 0; j < 256; j++) {
        ulonglong2 w0 = sW[2 * j], w1 = sW[2 * j + 1];
        ulonglong2 m0 = sM[2 * j], m1 = sM[2 * j + 1];
        float bj = sB[j];

        unsigned long long t0, t1;
        MUL2(t0, cA[0], w0.x); FMA2(t0, cA[1], w0.y, t0);
        MUL2(t1, cA[2], w1.x); FMA2(t1, cA[3], w1.y, t1);
        ADD2(t0, t0, t1);
        float lo, hi; upk2(t0, lo, hi);
        float hA = fmaxf(lo + hi + bj, 0.f);

        MUL2(t0, cB[0], w0.x); FMA2(t0, cB[1], w0.y, t0);
        MUL2(t1, cB[2], w1.x); FMA2(t1, cB[3], w1.y, t1);
        ADD2(t0, t0, t1);
        upk2(t0, lo, hi);
        float hB = fmaxf(lo + hi + bj, 0.f);

        unsigned long long hA2 = pk2(hA, hA);
        unsigned long long hB2 = pk2(hB, hB);
        FMA2(yA[0], hA2, m0.x, yA[0]); FMA2(yA[1], hA2, m0.y, yA[1]);
        FMA2(yA[2], hA2, m1.x, yA[2]); FMA2(yA[3], hA2, m1.y, yA[3]);
        FMA2(yB[0], hB2, m0.x, yB[0]); FMA2(yB[1], hB2, m0.y, yB[1]);
        FMA2(yB[2], hB2, m1.x, yB[2]); FMA2(yB[3], hB2, m1.y, yB[3]);
    }

    const unsigned long long H2b = HALF2C;
    const ulonglong4* eaq = (const ulonglong4*)ea;
    ulonglong4* outq = (ulonglong4*)out;

    if (vA) {
        ulonglong4 ev = eaq[eA];
        ulonglong4 ov;
        unsigned long long t;
        ADD2(t, yA[0], sC[0]); FMA2(ov.x, t, H2b, ev.x);
        ADD2(t, yA[1], sC[1]); FMA2(ov.y, t, H2b, ev.y);
        ADD2(t, yA[2], sC[2]); FMA2(ov.z, t, H2b, ev.z);
        ADD2(t, yA[3], sC[3]); FMA2(ov.w, t, H2b, ev.w);
        outq[eA] = ov;
    }
    if (vB) {
        ulonglong4 ev = eaq[eB];
        ulonglong4 ov;
        unsigned long long t;
        ADD2(t, yB[0], sC[0]); FMA2(ov.x, t, H2b, ev.x);
        ADD2(t, yB[1], sC[1]); FMA2(ov.y, t, H2b, ev.y);
        ADD2(t, yB[2], sC[2]); FMA2(ov.z, t, H2b, ev.z);
        ADD2(t, yB[3], sC[3]); FMA2(ov.w, t, H2b, ev.w);
        outq[eB] = ov;
    }
}

// ---------------------------------------------------------------------------
extern "C" void kernel_launch(void* const* d_in, const int* in_sizes, int n_in,
                              void* d_out, int out_size) {
    const float* edge_attr = (const float*)d_in[0];
    const float* nf        = (const float*)d_in[1];
    const int*   ei        = (const int*)d_in[2];
    // d_in[3..8]: edge-encoder params (dead code in reference)
    const float* nW1   = (const float*)d_in[9];
    const float* nb1   = (const float*)d_in[10];
    const float* ngam  = (const float*)d_in[11];
    const float* nbet  = (const float*)d_in[12];
    const float* nW2   = (const float*)d_in[13];
    const float* nb2   = (const float*)d_in[14];
    const float* Wv    = (const float*)d_in[15];
    const float* bv    = (const float*)d_in[16];
    const float* Wo    = (const float*)d_in[17];
    const float* bo    = (const float*)d_in[18];
    const float* Wp    = (const float*)d_in[19];
    const float* bp    = (const float*)d_in[20];
    float* out = (float*)d_out;

    int E = in_sizes[0] / 8;

    kStats<<<STATS_BLOCKS, 128>>>(nf, ei, nW1, nb1, E);
    kFoldFin<<<1, 1024>>>(Wo, Wp, nb2, Wv, bv, bo, nW2, bp, ngam, nbet,
                          1.0f / (float)E);
    kOut<<<(E + 511) / 512, 256>>>(nf, ei, nW1, nb1, edge_attr, out, E);
}